// round 5
// baseline (speedup 1.0000x reference)
#include <cuda_runtime.h>

#define T_LEN 8192
#define NB    16
#define NL    50

// ping-pong activation buffers: [pp][dir][batch][t]  (4 MB, static — allowed)
__device__ float g_act[2][2][NB][T_LEN];

__device__ __forceinline__ float ex2f_(float x) {
    float r; asm("ex2.approx.f32 %0, %1;" : "=f"(r) : "f"(x)); return r;
}
__device__ __forceinline__ float tanhf_(float x) {
    float r; asm("tanh.approx.f32 %0, %1;" : "=f"(r) : "f"(x)); return r;
}

// One direction of one layer for 4 sequences (one warp).
// Lanes: 4 groups of 8; lane j in group = hidden index j (5..7 mirror 4, unused).
template<bool REV, bool FIRST>
__device__ __forceinline__ void lstm_dir(
    const float* __restrict__ x,
    const float* __restrict__ Wih0,   // (2,20,1)
    const float* __restrict__ WihR,   // (49,2,20,2)
    const float* __restrict__ Whh,    // (50,2,20,1)
    const float* __restrict__ bih,    // (50,2,20)
    const float* __restrict__ bhh,    // (50,2,20)
    const float* __restrict__ Whr,    // (50,2,1,5)
    int layer, int b, int base, int jj)
{
    const int d  = REV ? 1 : 0;
    const int ld = layer * 2 + d;

    float whr[5];
#pragma unroll
    for (int q = 0; q < 5; q++) whr[q] = Whr[ld * 5 + q];

    // per-lane weights, gate order k = {i,f,g,o}, row = k*5 + jj.
    // sigmoid gates: sigmoid(z) = 0.5 + 0.5*tanh(z/2) -> fold 0.5 into weights.
    float wf[4], wb[4], bb[4], whh_s[4];
#pragma unroll
    for (int k = 0; k < 4; k++) {
        const float sk = (k == 2) ? 1.0f : 0.5f;
        const int   g  = k * 5 + jj;
        whh_s[k] = sk * Whh[ld * 20 + g];
        bb[k]    = sk * (bih[ld * 20 + g] + bhh[ld * 20 + g]);
        if (FIRST) {
            wf[k] = sk * Wih0[d * 20 + g];
            wb[k] = 0.0f;
        } else {
            wf[k] = sk * WihR[((ld - 2) * 20 + g) * 2 + 0];
            wb[k] = sk * WihR[((ld - 2) * 20 + g) * 2 + 1];
        }
    }

    const float* p0;
    const float* p1;
    if (FIRST) {
        p0 = x + b * T_LEN;
        p1 = p0;
    } else {
        const int pp = (layer - 1) & 1;
        p0 = &g_act[pp][0][b][0];
        p1 = &g_act[pp][1][b][0];
    }
    float* po = &g_act[layer & 1][d][b][0];

    const float4* q0 = (const float4*)p0;
    const float4* q1 = (const float4*)p1;
    const int NC = T_LEN / 4;

    float4 cur0 = __ldg(q0 + (REV ? NC - 1 : 0));
    float4 nxt0 = __ldg(q0 + (REV ? NC - 2 : 1));
    float4 cur1, nxt1;
    if (!FIRST) {
        cur1 = __ldg(q1 + (REV ? NC - 1 : 0));
        nxt1 = __ldg(q1 + (REV ? NC - 2 : 1));
    }

    float c = 0.0f, u = 0.0f, ch = 0.0f;   // ch = 0.5*c, maintained off-chain

    for (int sc = 0; sc < T_LEN; sc += 4) {
        const float4 i0 = cur0; cur0 = nxt0;
        float4 i1;
        if (!FIRST) { i1 = cur1; cur1 = nxt1; }

        // branch-free prefetch (min instead of if)
        int nci = (sc >> 2) + 2;
        nci = nci < NC - 1 ? nci : NC - 1;
        const int pf = REV ? (NC - 1 - nci) : nci;
        nxt0 = __ldg(q0 + pf);
        if (!FIRST) nxt1 = __ldg(q1 + pf);

        const float e0[4] = { i0.x, i0.y, i0.z, i0.w };
        float e1[4];
        if (!FIRST) { e1[0] = i1.x; e1[1] = i1.y; e1[2] = i1.z; e1[3] = i1.w; }

#pragma unroll
        for (int ss = 0; ss < 4; ss++) {
            const int s = sc + ss;
            const int e = REV ? (3 - ss) : ss;       // compile-time
            const float in0 = e0[e];

            // unconditional store index for h_{s-1}:
            //   FWD: max(s-1,0)      (s=0 writes slot 0, overwritten by s=1)
            //   REV: T_LEN - max(s,1) (s=0 writes T-1, overwritten by s=1)
            int sm1 = s - 1; sm1 = sm1 > 0 ? sm1 : 0;
            const int sto = REV ? (T_LEN - 1 - sm1) : sm1;

            // input contribution (off critical path)
            float pre[4];
#pragma unroll
            for (int k = 0; k < 4; k++) {
                pre[k] = fmaf(wf[k], in0, bb[k]);
                if (!FIRST) pre[k] = fmaf(wb[k], e1[e], pre[k]);
            }

            // gather u_{t-1} from the 5 active lanes of this group
            const float u0 = __shfl_sync(0xffffffffu, u, base + 0);
            const float u1 = __shfl_sync(0xffffffffu, u, base + 1);
            const float u2 = __shfl_sync(0xffffffffu, u, base + 2);
            const float u3 = __shfl_sync(0xffffffffu, u, base + 3);
            const float u4 = __shfl_sync(0xffffffffu, u, base + 4);

            // h = Whr . u  — serves BOTH the layer output and all 4 gates
            const float h = (fmaf(whr[0], u0, whr[1] * u1) +
                             fmaf(whr[2], u2, whr[3] * u3)) + whr[4] * u4;

            // gates first (critical path), ...
            const float ag = fmaf(whh_s[2], h, pre[2]);
            const float ai = fmaf(whh_s[0], h, pre[0]);
            const float af = fmaf(whh_s[1], h, pre[1]);
            const float ao = fmaf(whh_s[3], h, pre[3]);

            const float tg = tanhf_(ag);
            const float ti = tanhf_(ai);
            const float tf = tanhf_(af);
            const float to = tanhf_(ao);

            // ... h store after gate issue: all 8 lanes, same addr+value,
            // no predicate, no branch -> coalesces to one transaction.
            po[sto] = h;

            // c = sigmoid(f)*c + sigmoid(i)*g
            const float tgh = 0.5f * tg;
            const float iig = fmaf(ti, tgh, tgh);
            const float r   = ch + iig;
            c  = fmaf(tf, ch, r);
            ch = 0.5f * c;                           // off-chain for next step

            const float tc  = tanhf_(c);
            const float top = fmaf(0.5f, to, 0.5f);  // sigmoid(ao), off-chain
            u = tc * top;
        }
    }

    // epilogue: h for the final step (s = T_LEN-1), unconditional all lanes
    {
        const float u0 = __shfl_sync(0xffffffffu, u, base + 0);
        const float u1 = __shfl_sync(0xffffffffu, u, base + 1);
        const float u2 = __shfl_sync(0xffffffffu, u, base + 2);
        const float u3 = __shfl_sync(0xffffffffu, u, base + 3);
        const float u4 = __shfl_sync(0xffffffffu, u, base + 4);
        const float h = (fmaf(whr[0], u0, whr[1] * u1) +
                         fmaf(whr[2], u2, whr[3] * u3)) + whr[4] * u4;
        po[REV ? 0 : (T_LEN - 1)] = h;
    }
}

// grid = 8 blocks x 32 threads. Blocks 0-3: forward dir, batches 0-15.
// Blocks 4-7: reverse dir. Direction is compile-time per path.
__global__ void __launch_bounds__(32, 1) lstm_layer_kernel(
    const float* __restrict__ x,
    const float* __restrict__ Wih0,
    const float* __restrict__ WihR,
    const float* __restrict__ Whh,
    const float* __restrict__ bih,
    const float* __restrict__ bhh,
    const float* __restrict__ Whr,
    int layer)
{
    const int lane = threadIdx.x;
    const int grp  = lane >> 3;
    const int j    = lane & 7;
    const int jj   = (j > 4) ? 4 : j;
    const int base = grp * 8;
    const int b    = (blockIdx.x & 3) * 4 + grp;   // 0..15

    if (blockIdx.x < 4) {
        if (layer == 0) lstm_dir<false, true >(x, Wih0, WihR, Whh, bih, bhh, Whr, layer, b, base, jj);
        else            lstm_dir<false, false>(x, Wih0, WihR, Whh, bih, bhh, Whr, layer, b, base, jj);
    } else {
        if (layer == 0) lstm_dir<true,  true >(x, Wih0, WihR, Whh, bih, bhh, Whr, layer, b, base, jj);
        else            lstm_dir<true,  false>(x, Wih0, WihR, Whh, bih, bhh, Whr, layer, b, base, jj);
    }
}

// final: ss = fwd+bwd; out[b][0][t] = sigmoid(2ss-1) via softmax identity
__global__ void finalize_kernel(float* __restrict__ out)
{
    const int idx = blockIdx.x * blockDim.x + threadIdx.x;
    if (idx >= NB * T_LEN) return;
    const int b = idx / T_LEN;
    const int t = idx - b * T_LEN;
    const int pp = (NL - 1) & 1;
    const float ss = g_act[pp][0][b][t] + g_act[pp][1][b][t];
    const float e  = ex2f_((1.0f - 2.0f * ss) * 1.4426950408889634f);
    const float p0v = 1.0f / (1.0f + e);
    out[(b * 2 + 0) * T_LEN + t] = p0v;
    out[(b * 2 + 1) * T_LEN + t] = 1.0f - p0v;
}

extern "C" void kernel_launch(void* const* d_in, const int* in_sizes, int n_in,
                              void* d_out, int out_size)
{
    const float* x    = (const float*)d_in[0];
    const float* Wih0 = (const float*)d_in[1];
    const float* WihR = (const float*)d_in[2];
    const float* Whh  = (const float*)d_in[3];
    const float* bih  = (const float*)d_in[4];
    const float* bhh  = (const float*)d_in[5];
    const float* Whr  = (const float*)d_in[6];

    for (int l = 0; l < NL; l++) {
        lstm_layer_kernel<<<8, 32>>>(x, Wih0, WihR, Whh, bih, bhh, Whr, l);
    }
    finalize_kernel<<<(NB * T_LEN + 255) / 256, 256>>>((float*)d_out);
}

// round 6
// speedup vs baseline: 1.0601x; 1.0601x over previous
#include <cuda_runtime.h>

#define T_LEN 8192
#define NB    16
#define NL    50

// ping-pong activation buffers: [pp][dir][batch][t]  (4 MB, static — allowed)
__device__ float g_act[2][2][NB][T_LEN];

__device__ __forceinline__ float ex2f_(float x) {
    float r; asm("ex2.approx.f32 %0, %1;" : "=f"(r) : "f"(x)); return r;
}
__device__ __forceinline__ float tanhf_(float x) {
    float r; asm("tanh.approx.f32 %0, %1;" : "=f"(r) : "f"(x)); return r;
}

// One direction of one layer for 4 sequences (one warp).
// Lanes: 4 groups of 8; lane j in group = hidden index j (5..7 mirror 4).
template<bool REV, bool FIRST>
__device__ __forceinline__ void lstm_dir(
    const float* __restrict__ x,
    const float* __restrict__ Wih0,   // (2,20,1)
    const float* __restrict__ WihR,   // (49,2,20,2)
    const float* __restrict__ Whh,    // (50,2,20,1)
    const float* __restrict__ bih,    // (50,2,20)
    const float* __restrict__ bhh,    // (50,2,20)
    const float* __restrict__ Whr,    // (50,2,1,5)
    int layer, int b, int base, int jj)
{
    const int d  = REV ? 1 : 0;
    const int ld = layer * 2 + d;

    // rotated gather: lane jj pulls u from (jj+m)%5, m=1..4; own u is local.
    int src[4];
    int rot[4];
#pragma unroll
    for (int m = 0; m < 4; m++) {
        rot[m] = (jj + 1 + m) % 5;
        src[m] = base + rot[m];
    }

    float whr_all[5];
#pragma unroll
    for (int q = 0; q < 5; q++) whr_all[q] = Whr[ld * 5 + q];
    const float whr_own = whr_all[jj];
    float whr_r[4];
#pragma unroll
    for (int m = 0; m < 4; m++) whr_r[m] = whr_all[rot[m]];

    // per-lane weights, gate order k = {i,f,g,o}, row = k*5 + jj.
    // sigmoid gates: sigmoid(z) = 0.5 + 0.5*tanh(z/2) -> fold 0.5 into weights.
    // M-form: M[k][q] = sk * whh_k * whr_q, rotated to arrival order.
    float wf[4], wb[4], bb[4], Mo[4], Mr[4][4];
#pragma unroll
    for (int k = 0; k < 4; k++) {
        const float sk = (k == 2) ? 1.0f : 0.5f;
        const int   g  = k * 5 + jj;
        const float whh = sk * Whh[ld * 20 + g];
        bb[k] = sk * (bih[ld * 20 + g] + bhh[ld * 20 + g]);
        if (FIRST) {
            wf[k] = sk * Wih0[d * 20 + g];
            wb[k] = 0.0f;
        } else {
            wf[k] = sk * WihR[((ld - 2) * 20 + g) * 2 + 0];
            wb[k] = sk * WihR[((ld - 2) * 20 + g) * 2 + 1];
        }
        Mo[k] = whh * whr_own;
#pragma unroll
        for (int m = 0; m < 4; m++) Mr[k][m] = whh * whr_r[m];
    }

    const float* p0;
    const float* p1;
    if (FIRST) {
        p0 = x + b * T_LEN;
        p1 = p0;
    } else {
        const int pp = (layer - 1) & 1;
        p0 = &g_act[pp][0][b][0];
        p1 = &g_act[pp][1][b][0];
    }
    float* po = &g_act[layer & 1][d][b][0];

    const float4* q0 = (const float4*)p0;
    const float4* q1 = (const float4*)p1;
    const int NC = T_LEN / 4;

    float4 cur0 = __ldg(q0 + (REV ? NC - 1 : 0));
    float4 nxt0 = __ldg(q0 + (REV ? NC - 2 : 1));
    float4 cur1, nxt1;
    if (!FIRST) {
        cur1 = __ldg(q1 + (REV ? NC - 1 : 0));
        nxt1 = __ldg(q1 + (REV ? NC - 2 : 1));
    }

    float c = 0.0f, u = 0.0f, ch = 0.0f;   // ch = 0.5*c, maintained off-chain

    for (int sc = 0; sc < T_LEN; sc += 4) {
        const float4 i0 = cur0; cur0 = nxt0;
        float4 i1;
        if (!FIRST) { i1 = cur1; cur1 = nxt1; }

        // branch-free prefetch
        int nci = (sc >> 2) + 2;
        nci = nci < NC - 1 ? nci : NC - 1;
        const int pf = REV ? (NC - 1 - nci) : nci;
        nxt0 = __ldg(q0 + pf);
        if (!FIRST) nxt1 = __ldg(q1 + pf);

        const float e0[4] = { i0.x, i0.y, i0.z, i0.w };
        float e1[4];
        if (!FIRST) { e1[0] = i1.x; e1[1] = i1.y; e1[2] = i1.z; e1[3] = i1.w; }

#pragma unroll
        for (int ss = 0; ss < 4; ss++) {
            const int s = sc + ss;
            const int e = REV ? (3 - ss) : ss;       // compile-time
            const float in0 = e0[e];

            // unconditional store index for h_{s-1}
            int sm1 = s - 1; sm1 = sm1 > 0 ? sm1 : 0;
            const int sto = REV ? (T_LEN - 1 - sm1) : sm1;

            // input contribution (off critical path)
            float pre[4];
#pragma unroll
            for (int k = 0; k < 4; k++) {
                pre[k] = fmaf(wf[k], in0, bb[k]);
                if (!FIRST) pre[k] = fmaf(wb[k], e1[e], pre[k]);
            }

            // own-lane contribution issues before gathers land
            float own[4];
#pragma unroll
            for (int k = 0; k < 4; k++) own[k] = fmaf(Mo[k], u, pre[k]);

            // 4 gathers (own u is local)
            const float v1 = __shfl_sync(0xffffffffu, u, src[0]);
            const float v2 = __shfl_sync(0xffffffffu, u, src[1]);
            const float v3 = __shfl_sync(0xffffffffu, u, src[2]);
            const float v4 = __shfl_sync(0xffffffffu, u, src[3]);

            // gate pre-activations: consume v's in arrival order.
            // Order tanh issue g,i,f,o for the c-path.
            float a[4];
#pragma unroll
            for (int k = 0; k < 4; k++) {
                float t = fmaf(Mr[k][0], v1, own[k]);
                t = fmaf(Mr[k][1], v2, t);
                t = fmaf(Mr[k][2], v3, t);
                a[k] = fmaf(Mr[k][3], v4, t);
            }

            const float tg = tanhf_(a[2]);
            const float ti = tanhf_(a[0]);
            const float tf = tanhf_(a[1]);
            const float to = tanhf_(a[3]);

            // h = Whr . u_{t-1}  (off critical path, store after tanh issue)
            float h = fmaf(whr_own, u, whr_r[0] * v1);
            h = fmaf(whr_r[1], v2, h);
            h = fmaf(whr_r[2], v3, h);
            h = fmaf(whr_r[3], v4, h);
            po[sto] = h;

            // c = sigmoid(f)*c + sigmoid(i)*g
            const float tgh = 0.5f * tg;
            const float iig = fmaf(ti, tgh, tgh);
            const float r   = ch + iig;
            c  = fmaf(tf, ch, r);
            ch = 0.5f * c;                           // off-chain for next step

            const float tc  = tanhf_(c);
            const float top = fmaf(0.5f, to, 0.5f);  // sigmoid(ao), off-chain
            u = tc * top;
        }
    }

    // epilogue: h for the final step (s = T_LEN-1), unconditional all lanes
    {
        const float v1 = __shfl_sync(0xffffffffu, u, src[0]);
        const float v2 = __shfl_sync(0xffffffffu, u, src[1]);
        const float v3 = __shfl_sync(0xffffffffu, u, src[2]);
        const float v4 = __shfl_sync(0xffffffffu, u, src[3]);
        float h = fmaf(whr_own, u, whr_r[0] * v1);
        h = fmaf(whr_r[1], v2, h);
        h = fmaf(whr_r[2], v3, h);
        h = fmaf(whr_r[3], v4, h);
        po[REV ? 0 : (T_LEN - 1)] = h;
    }
}

// grid = 8 blocks x 32 threads. Blocks 0-3: forward dir, batches 0-15.
// Blocks 4-7: reverse dir. Direction is compile-time per path.
__global__ void __launch_bounds__(32, 1) lstm_layer_kernel(
    const float* __restrict__ x,
    const float* __restrict__ Wih0,
    const float* __restrict__ WihR,
    const float* __restrict__ Whh,
    const float* __restrict__ bih,
    const float* __restrict__ bhh,
    const float* __restrict__ Whr,
    int layer)
{
    const int lane = threadIdx.x;
    const int grp  = lane >> 3;
    const int j    = lane & 7;
    const int jj   = (j > 4) ? 4 : j;
    const int base = grp * 8;
    const int b    = (blockIdx.x & 3) * 4 + grp;   // 0..15

    if (blockIdx.x < 4) {
        if (layer == 0) lstm_dir<false, true >(x, Wih0, WihR, Whh, bih, bhh, Whr, layer, b, base, jj);
        else            lstm_dir<false, false>(x, Wih0, WihR, Whh, bih, bhh, Whr, layer, b, base, jj);
    } else {
        if (layer == 0) lstm_dir<true,  true >(x, Wih0, WihR, Whh, bih, bhh, Whr, layer, b, base, jj);
        else            lstm_dir<true,  false>(x, Wih0, WihR, Whh, bih, bhh, Whr, layer, b, base, jj);
    }
}

// final: ss = fwd+bwd; out[b][0][t] = sigmoid(2ss-1) via softmax identity
__global__ void finalize_kernel(float* __restrict__ out)
{
    const int idx = blockIdx.x * blockDim.x + threadIdx.x;
    if (idx >= NB * T_LEN) return;
    const int b = idx / T_LEN;
    const int t = idx - b * T_LEN;
    const int pp = (NL - 1) & 1;
    const float ss = g_act[pp][0][b][t] + g_act[pp][1][b][t];
    const float e  = ex2f_((1.0f - 2.0f * ss) * 1.4426950408889634f);
    const float p0v = 1.0f / (1.0f + e);
    out[(b * 2 + 0) * T_LEN + t] = p0v;
    out[(b * 2 + 1) * T_LEN + t] = 1.0f - p0v;
}

extern "C" void kernel_launch(void* const* d_in, const int* in_sizes, int n_in,
                              void* d_out, int out_size)
{
    const float* x    = (const float*)d_in[0];
    const float* Wih0 = (const float*)d_in[1];
    const float* WihR = (const float*)d_in[2];
    const float* Whh  = (const float*)d_in[3];
    const float* bih  = (const float*)d_in[4];
    const float* bhh  = (const float*)d_in[5];
    const float* Whr  = (const float*)d_in[6];

    for (int l = 0; l < NL; l++) {
        lstm_layer_kernel<<<8, 32>>>(x, Wih0, WihR, Whh, bih, bhh, Whr, l);
    }
    finalize_kernel<<<(NB * T_LEN + 255) / 256, 256>>>((float*)d_out);
}